// round 14
// baseline (speedup 1.0000x reference)
#include <cuda_runtime.h>
#include <cuda_fp16.h>
#include <math.h>
#include <stdint.h>

#define B_ 32
#define T_ 1024
#define C_ 512
#define H_ 256

// ---------------- static device scratch ----------------
__device__ float g_bufA[(size_t)B_ * T_ * C_];                 // fp32 conv output
__device__ __half g_h16[(size_t)B_ * T_ * C_];                 // fp16 GEMM input acts
__device__ float g_xg[(size_t)2 * B_ * T_ * 4 * H_];
__device__ float g_hs[(size_t)2 * T_ * B_ * H_];
__device__ __half g_wT16[(size_t)3 * 5 * 512 * 512];           // conv W [d][tap][co][ci] fp16
__device__ __half g_wxT16[(size_t)2 * 1024 * 512];             // wx [dir][gatecol][ci] fp16
__device__ unsigned int g_flags[128];

// ---------------- helpers ----------------
__device__ __forceinline__ uint32_t smem_u32(const void* p) {
    uint32_t a;
    asm("{ .reg .u64 t; cvta.to.shared.u64 t, %1; cvt.u32.u64 %0, t; }" : "=r"(a) : "l"(p));
    return a;
}
__device__ __forceinline__ void cp16(uint32_t dst, const void* src, int srcsz) {
    asm volatile("cp.async.cg.shared.global [%0], [%1], 16, %2;"
                 :: "r"(dst), "l"(src), "r"(srcsz));
}
#define CP_COMMIT() asm volatile("cp.async.commit_group;")
#define CP_WAIT2()  asm volatile("cp.async.wait_group 2;")

__device__ __forceinline__ void mma_f16(float& c0, float& c1, float& c2, float& c3,
                                        uint32_t a0, uint32_t a1, uint32_t a2, uint32_t a3,
                                        uint32_t b0, uint32_t b1) {
    asm volatile(
        "mma.sync.aligned.m16n8k16.row.col.f32.f16.f16.f32 "
        "{%0,%1,%2,%3}, {%4,%5,%6,%7}, {%8,%9}, {%0,%1,%2,%3};"
        : "+f"(c0), "+f"(c1), "+f"(c2), "+f"(c3)
        : "r"(a0), "r"(a1), "r"(a2), "r"(a3), "r"(b0), "r"(b1));
}

__device__ __forceinline__ void ldsm_x4(uint32_t& r0, uint32_t& r1, uint32_t& r2, uint32_t& r3,
                                        uint32_t addr) {
    asm volatile("ldmatrix.sync.aligned.m8n8.x4.shared.b16 {%0,%1,%2,%3}, [%4];"
                 : "=r"(r0), "=r"(r1), "=r"(r2), "=r"(r3) : "r"(addr));
}

// packed fp32 pair FMA (Blackwell sm_100+, PTX 8.6)
__device__ __forceinline__ void fma2(uint64_t& acc, uint64_t a, uint64_t b) {
    asm("fma.rn.f32x2 %0, %1, %2, %0;" : "+l"(acc) : "l"(a), "l"(b));
}
__device__ __forceinline__ float pairsum(uint64_t a) {
    float lo, hi;
    asm("mov.b64 {%0, %1}, %2;" : "=f"(lo), "=f"(hi) : "l"(a));
    return lo + hi;
}

// ---------------- weight transpose -> fp16 ----------------
__global__ void transpose_half_kernel(const float* __restrict__ src, __half* __restrict__ dst,
                                      int R, int Cc) {
    __shared__ float t[32][33];
    const size_t slab = (size_t)R * Cc;
    const float* s = src + (size_t)blockIdx.z * slab;
    __half* d = dst + (size_t)blockIdx.z * slab;
    int c0 = blockIdx.x * 32, r0 = blockIdx.y * 32;
    int x = threadIdx.x, y = threadIdx.y;
#pragma unroll
    for (int i = y; i < 32; i += 8)
        t[i][x] = s[(size_t)(r0 + i) * Cc + c0 + x];
    __syncthreads();
#pragma unroll
    for (int i = y; i < 32; i += 8)
        d[(size_t)(c0 + i) * R + r0 + x] = __float2half(t[x][i]);
}

// ---------------- embedding -> fp16 acts ----------------
__global__ void embed_kernel(const int* __restrict__ x,
                             const unsigned char* __restrict__ m,
                             const float* __restrict__ emb) {
    size_t i = (size_t)blockIdx.x * blockDim.x + threadIdx.x;
    size_t bt = i / C_;
    int c = (int)(i % C_);
    int sym = x[bt];
    float v = emb[(size_t)sym * C_ + c];
    if (m[bt]) v = 0.f;
    g_h16[i] = __float2half(v);
}

// ---------------- fp16 mma.sync GEMM / implicit conv (R8 config: 128x128, 4-stage) ----
#define LDKH 40
#define TILEH (128 * LDKH)
#define STAGEH (2 * TILEH)
#define NSTG 4
#define GEMM_SMEM (NSTG * STAGEH * 2)

template <int TAPS>
__global__ __launch_bounds__(256) void mma_gemm_fp16(
    const __half* __restrict__ A,
    const __half* __restrict__ WT, const float* __restrict__ bias, float* __restrict__ Out,
    int Cout,
    const __half* __restrict__ WT2, const float* __restrict__ bias2, float* __restrict__ Out2) {
    extern __shared__ __half shh[];

    if (blockIdx.z) { WT = WT2; bias = bias2; Out = Out2; }

    const int tid = threadIdx.x;
    const int wid = tid >> 5, lane = tid & 31;
    const int r = lane >> 2, cq = lane & 3;
    const int warp_m = wid & 1, warp_n = wid >> 1;
    const int m0 = warp_m * 64, n0 = warp_n * 32;

    const int bb = blockIdx.x >> 3;
    const int t0 = (blockIdx.x & 7) * 128;
    const int co0 = blockIdx.y * 128;
    const int NT = TAPS * 16;
    const int half = (TAPS - 1) / 2;

    float acc[4][4][4];
#pragma unroll
    for (int i = 0; i < 4; i++)
#pragma unroll
        for (int j = 0; j < 4; j++)
#pragma unroll
            for (int k = 0; k < 4; k++) acc[i][j][k] = 0.f;

    const uint32_t shb = smem_u32(shh);

    const uint32_t aOff = (uint32_t)(((m0 + (lane & 15)) * LDKH) * 2 + (lane >> 4) * 16);
    const uint32_t bOff = (uint32_t)(TILEH * 2 +
                         ((n0 + ((lane >> 3) & 1) * 8 + (lane & 7)) * LDKH) * 2 + (lane >> 4) * 16);

    auto load_tile = [&](int tidx, int stage) {
        const uint32_t sbase = shb + stage * (STAGEH * 2);
        const int tap = (TAPS == 1) ? 0 : (tidx >> 4);
        const int kt = (TAPS == 1) ? tidx : (tidx & 15);
        const __half* Ab = A + (size_t)bb * T_ * C_ + kt * 32;
#pragma unroll
        for (int it = 0; it < 2; it++) {
            int chunk = it * 256 + tid;
            int row = chunk >> 2, seg = chunk & 3;
            int t = t0 + row + tap - half;
            int ok = ((unsigned)t < (unsigned)T_) ? 16 : 0;
            int tc = t < 0 ? 0 : (t > T_ - 1 ? T_ - 1 : t);
            cp16(sbase + (row * LDKH + seg * 8) * 2, Ab + (size_t)tc * C_ + seg * 8, ok);
        }
        const __half* Bb = WT + ((size_t)tap * Cout + co0) * C_ + kt * 32;
#pragma unroll
        for (int it = 0; it < 2; it++) {
            int chunk = it * 256 + tid;
            int row = chunk >> 2, seg = chunk & 3;
            cp16(sbase + TILEH * 2 + (row * LDKH + seg * 8) * 2,
                 Bb + (size_t)row * C_ + seg * 8, 16);
        }
    };

    load_tile(0, 0); CP_COMMIT();
    load_tile(1, 1); CP_COMMIT();
    load_tile(2, 2); CP_COMMIT();

    for (int t = 0; t < NT; t++) {
        CP_WAIT2();
        __syncthreads();
        if (t + 3 < NT) load_tile(t + 3, (t + 3) & 3);
        CP_COMMIT();

        const uint32_t stg = shb + (t & 3) * (STAGEH * 2);
#pragma unroll
        for (int ks = 0; ks < 2; ks++) {
            const uint32_t kB = (uint32_t)(ks * 32);
            uint32_t af[4][4], bf[4][2];
#pragma unroll
            for (int i = 0; i < 4; i++)
                ldsm_x4(af[i][0], af[i][1], af[i][2], af[i][3],
                        stg + aOff + (uint32_t)(i * 16 * LDKH * 2) + kB);
#pragma unroll
            for (int jj = 0; jj < 2; jj++)
                ldsm_x4(bf[2 * jj][0], bf[2 * jj + 1][0], bf[2 * jj][1], bf[2 * jj + 1][1],
                        stg + bOff + (uint32_t)(jj * 16 * LDKH * 2) + kB);
#pragma unroll
            for (int i = 0; i < 4; i++)
#pragma unroll
                for (int j = 0; j < 4; j++)
                    mma_f16(acc[i][j][0], acc[i][j][1], acc[i][j][2], acc[i][j][3],
                            af[i][0], af[i][1], af[i][2], af[i][3], bf[j][0], bf[j][1]);
        }
    }

#pragma unroll
    for (int j = 0; j < 4; j++) {
        const int col = co0 + n0 + j * 8 + 2 * cq;
        const float bv0 = bias[col], bv1 = bias[col + 1];
#pragma unroll
        for (int i = 0; i < 4; i++) {
            int row = t0 + m0 + i * 16 + r;
            float2 v0 = make_float2(acc[i][j][0] + bv0, acc[i][j][1] + bv1);
            float2 v1 = make_float2(acc[i][j][2] + bv0, acc[i][j][3] + bv1);
            *(float2*)(Out + ((size_t)bb * T_ + row) * Cout + col) = v0;
            *(float2*)(Out + ((size_t)bb * T_ + row + 8) * Cout + col) = v1;
        }
    }
}

// ---------------- LayerNorm over time + leaky relu + mask -> fp16 acts ----------------
__global__ void ln_lrelu_kernel(const float* __restrict__ h, __half* __restrict__ o16,
                                const float* __restrict__ scale,
                                const float* __restrict__ bias,
                                const unsigned char* __restrict__ m) {
    const int b = blockIdx.x;
    const int c = blockIdx.y * 128 + threadIdx.x;
    const float* hb = h + (size_t)b * T_ * C_ + c;
    __half* ob = o16 + (size_t)b * T_ * C_ + c;
    float s = 0.f, s2 = 0.f;
#pragma unroll 8
    for (int t = 0; t < T_; t++) {
        float v = hb[(size_t)t * C_];
        s += v; s2 += v * v;
    }
    const float mu = s * (1.f / T_);
    const float var = s2 * (1.f / T_) - mu * mu;
    const float rs = rsqrtf(var + 1e-5f);
    const unsigned char* mb = m + (size_t)b * T_;
#pragma unroll 4
    for (int t = 0; t < T_; t++) {
        float v = hb[(size_t)t * C_];
        v = (v - mu) * rs * scale[t] + bias[t];
        v = (v > 0.f) ? v : 0.2f * v;
        if (mb[t]) v = 0.f;
        ob[(size_t)t * C_] = __float2half(v);
    }
}

// ---------------- flag reset (graph-replay safe) ----------------
__global__ void reset_flags_kernel() {
    if (threadIdx.x < 128) g_flags[threadIdx.x] = 0;
}

// ---------------- bidirectional LSTM recurrence ----------------
// R7 exchange (fence + flag + __ldcg), localized per thread: each consumer thread
// spins on ONLY its source hg's flag, then immediately loads its own 2 h words.
// Producer unchanged: STG h -> __threadfence (release) -> barrier -> tid0 flag STG.
__global__ __launch_bounds__(512) void lstm_kernel(const float* __restrict__ wh_fw,
                                                   const float* __restrict__ wh_bw) {
    __shared__ float hps[1024];          // [4 batch][256]
    __shared__ float part[4 * 4 * 128];  // [kq][bl][g]
    __shared__ float cbuf[128];          // [bi][u]

    const int tid = threadIdx.x;
    const int dir = blockIdx.x >> 6;
    const int bg = (blockIdx.x >> 3) & 7;
    const int hg = blockIdx.x & 7;
    const int u0 = hg * 32;
    const int b0 = bg * 4;

    const int g = tid & 127;
    const int kq = tid >> 7;
    const int q = g >> 5;
    const int j = g & 31;
    const int col = q * 256 + u0 + j;

    const float* wh = dir ? wh_bw : wh_fw;
    uint64_t wreg[32];
#pragma unroll
    for (int k2 = 0; k2 < 32; k2++) {
        float w0 = wh[(size_t)(kq * 64 + 2 * k2) * 1024 + col];
        float w1 = wh[(size_t)(kq * 64 + 2 * k2 + 1) * 1024 + col];
        asm("mov.b64 %0, {%1, %2};" : "=l"(wreg[k2]) : "f"(w0), "f"(w1));
    }

    for (int i = tid; i < 1024; i += 512) hps[i] = 0.f;
    if (tid < 128) cbuf[tid] = 0.f;
    __syncthreads();

    const int u = tid & 31;
    const int bi = (tid >> 5) & 3;
    // source hg for this thread's two h words (pair never crosses a 32-unit block)
    const int src_hg = ((2 * tid) & 255) >> 5;

    const float* xgd = g_xg + (size_t)dir * B_ * T_ * 1024;
    float* hsd = g_hs + (size_t)dir * T_ * B_ * H_;
    volatile unsigned int* flg = (volatile unsigned int*)(g_flags + dir * 64 + bg * 8);

    for (int s = 0; s < T_; s++) {
        const int t = dir ? (T_ - 1 - s) : s;
        float xv = xgd[((size_t)(b0 + kq) * T_ + t) * 1024 + col];   // overlaps the spin

        if (s > 0) {
            while (flg[src_hg] < (unsigned)s) { }
            const int tprev = dir ? (t + 1) : (t - 1);
            const float2* src = (const float2*)(hsd + ((size_t)tprev * B_ + b0) * H_);
            ((float2*)hps)[tid] = __ldcg(src + tid);   // issued after flag observed
        }
        __syncthreads();

        const float* hq = hps + kq * 64;
        uint64_t a0 = 0, a1 = 0, a2 = 0, a3 = 0;
#pragma unroll
        for (int k2 = 0; k2 < 64; k2 += 4) {
            union U { float4 f; uint64_t u[2]; };
            U ha, hb, hc, hd;
            ha.f = *(const float4*)(hq + k2);
            hb.f = *(const float4*)(hq + 256 + k2);
            hc.f = *(const float4*)(hq + 512 + k2);
            hd.f = *(const float4*)(hq + 768 + k2);
            uint64_t w0 = wreg[k2 >> 1], w1 = wreg[(k2 >> 1) + 1];
            fma2(a0, w0, ha.u[0]); fma2(a0, w1, ha.u[1]);
            fma2(a1, w0, hb.u[0]); fma2(a1, w1, hb.u[1]);
            fma2(a2, w0, hc.u[0]); fma2(a2, w1, hc.u[1]);
            fma2(a3, w0, hd.u[0]); fma2(a3, w1, hd.u[1]);
        }
        part[(kq * 4 + 0) * 128 + g] = pairsum(a0) + ((kq == 0) ? xv : 0.f);
        part[(kq * 4 + 1) * 128 + g] = pairsum(a1) + ((kq == 1) ? xv : 0.f);
        part[(kq * 4 + 2) * 128 + g] = pairsum(a2) + ((kq == 2) ? xv : 0.f);
        part[(kq * 4 + 3) * 128 + g] = pairsum(a3) + ((kq == 3) ? xv : 0.f);
        __syncthreads();

        if (tid < 128) {
            float gate[4];
#pragma unroll
            for (int qq = 0; qq < 4; qq++) {
                float sum = part[(0 * 4 + bi) * 128 + qq * 32 + u]
                          + part[(1 * 4 + bi) * 128 + qq * 32 + u]
                          + part[(2 * 4 + bi) * 128 + qq * 32 + u]
                          + part[(3 * 4 + bi) * 128 + qq * 32 + u];
                gate[qq] = (qq == 2) ? tanhf(sum) : (1.f / (1.f + expf(-sum)));
            }
            float cc = gate[1] * cbuf[tid] + gate[0] * gate[2];
            cbuf[tid] = cc;
            float hn = gate[3] * tanhf(cc);
            hsd[((size_t)t * B_ + b0 + bi) * H_ + u0 + u] = hn;
            __threadfence();   // release: h visible in L2 before the flag below
        }
        __syncthreads();
        if (tid == 0) flg[hg] = (unsigned)(s + 1);
    }
}

// ---------------- output transpose [2][T][B][H] -> [B, 2H, T] ----------------
__global__ void out_kernel(float* __restrict__ out, const unsigned char* __restrict__ m) {
    const int dir = blockIdx.y >> 3;
    const int h0 = (blockIdx.y & 7) * 32;
    const int t0 = blockIdx.x * 32;
    const int b = blockIdx.z;
    __shared__ float tile[32][33];
    const float* hsd = g_hs + (size_t)dir * T_ * B_ * H_;
    const int tx = threadIdx.x, ty = threadIdx.y;
#pragma unroll
    for (int r = 0; r < 32; r += 8) {
        int t = t0 + ty + r;
        tile[ty + r][tx] = hsd[((size_t)t * B_ + b) * H_ + h0 + tx];
    }
    __syncthreads();
#pragma unroll
    for (int r = 0; r < 32; r += 8) {
        int hh = ty + r;
        int c = dir * H_ + h0 + hh;
        int t = t0 + tx;
        float v = tile[tx][hh];
        if (m[(size_t)b * T_ + t]) v = 0.f;
        out[((size_t)b * C_ + c) * T_ + t] = v;
    }
}

// ---------------- launch ----------------
extern "C" void kernel_launch(void* const* d_in, const int* in_sizes, int n_in,
                              void* d_out, int out_size) {
    const int* x = (const int*)d_in[0];
    const unsigned char* m = (const unsigned char*)d_in[2];
    const float* emb = (const float*)d_in[3];
    const float* conv_w = (const float*)d_in[4];
    const float* conv_b = (const float*)d_in[5];
    const float* ln_scale = (const float*)d_in[6];
    const float* ln_bias = (const float*)d_in[7];
    const float* wx_fw = (const float*)d_in[8];
    const float* wh_fw = (const float*)d_in[9];
    const float* b_fw = (const float*)d_in[10];
    const float* wx_bw = (const float*)d_in[11];
    const float* wh_bw = (const float*)d_in[12];
    const float* b_bw = (const float*)d_in[13];
    float* out = (float*)d_out;

    float *bufA, *xg;
    __half *h16, *wT16, *wxT16;
    cudaGetSymbolAddress((void**)&bufA, g_bufA);
    cudaGetSymbolAddress((void**)&xg, g_xg);
    cudaGetSymbolAddress((void**)&h16, g_h16);
    cudaGetSymbolAddress((void**)&wT16, g_wT16);
    cudaGetSymbolAddress((void**)&wxT16, g_wxT16);

    cudaFuncSetAttribute(mma_gemm_fp16<5>, cudaFuncAttributeMaxDynamicSharedMemorySize, GEMM_SMEM);
    cudaFuncSetAttribute(mma_gemm_fp16<1>, cudaFuncAttributeMaxDynamicSharedMemorySize, GEMM_SMEM);

    // launch order keeps the first conv GEMM at the ncu capture slot (my 4th launch)
    embed_kernel<<<(int)(((size_t)B_ * T_ * C_) / 256), 256>>>(x, m, emb);
    transpose_half_kernel<<<dim3(16, 16, 15), dim3(32, 8)>>>(conv_w, wT16, 512, 512);
    transpose_half_kernel<<<dim3(32, 16, 1), dim3(32, 8)>>>(wx_fw, wxT16, 512, 1024);

    for (int d = 0; d < 3; d++) {
        mma_gemm_fp16<5><<<dim3(B_ * 8, 4, 1), 256, GEMM_SMEM>>>(
            h16, wT16 + (size_t)d * 5 * 512 * 512, conv_b + (size_t)d * 512, bufA, 512,
            wT16, conv_b, bufA);
        ln_lrelu_kernel<<<dim3(B_, 4), 128>>>(bufA, h16, ln_scale + (size_t)d * T_,
                                              ln_bias + (size_t)d * T_, m);
    }

    transpose_half_kernel<<<dim3(32, 16, 1), dim3(32, 8)>>>(wx_bw, wxT16 + (size_t)1024 * 512, 512, 1024);

    mma_gemm_fp16<1><<<dim3(B_ * 8, 8, 2), 256, GEMM_SMEM>>>(
        h16, wxT16, b_fw, xg, 1024,
        wxT16 + (size_t)1024 * 512, b_bw, xg + (size_t)B_ * T_ * 1024);

    // recurrence (regs-W, f32x2, per-thread flag exchange)
    reset_flags_kernel<<<1, 128>>>();
    lstm_kernel<<<128, 512>>>(wh_fw, wh_bw);

    out_kernel<<<dim3(T_ / 32, 16, B_), dim3(32, 8)>>>(out, m);
}

// round 15
// speedup vs baseline: 1.0768x; 1.0768x over previous
#include <cuda_runtime.h>
#include <cuda_fp16.h>
#include <math.h>
#include <stdint.h>

#define B_ 32
#define T_ 1024
#define C_ 512
#define H_ 256

// ---------------- static device scratch ----------------
__device__ float g_bufA[(size_t)B_ * T_ * C_];                 // fp32 conv output
__device__ __half g_h16[(size_t)B_ * T_ * C_];                 // fp16 GEMM input acts
__device__ float g_xg[(size_t)2 * B_ * T_ * 4 * H_];
__device__ float g_hs[(size_t)2 * T_ * B_ * H_];
__device__ __half g_wT16[(size_t)3 * 5 * 512 * 512];           // conv W [d][tap][co][ci] fp16
__device__ __half g_wxT16[(size_t)2 * 1024 * 512];             // wx [dir][gatecol][ci] fp16
__device__ unsigned int g_flags[128];

// ---------------- helpers ----------------
__device__ __forceinline__ uint32_t smem_u32(const void* p) {
    uint32_t a;
    asm("{ .reg .u64 t; cvta.to.shared.u64 t, %1; cvt.u32.u64 %0, t; }" : "=r"(a) : "l"(p));
    return a;
}
__device__ __forceinline__ void cp16(uint32_t dst, const void* src, int srcsz) {
    asm volatile("cp.async.cg.shared.global [%0], [%1], 16, %2;"
                 :: "r"(dst), "l"(src), "r"(srcsz));
}
#define CP_COMMIT() asm volatile("cp.async.commit_group;")
#define CP_WAIT2()  asm volatile("cp.async.wait_group 2;")

__device__ __forceinline__ void mma_f16(float& c0, float& c1, float& c2, float& c3,
                                        uint32_t a0, uint32_t a1, uint32_t a2, uint32_t a3,
                                        uint32_t b0, uint32_t b1) {
    asm volatile(
        "mma.sync.aligned.m16n8k16.row.col.f32.f16.f16.f32 "
        "{%0,%1,%2,%3}, {%4,%5,%6,%7}, {%8,%9}, {%0,%1,%2,%3};"
        : "+f"(c0), "+f"(c1), "+f"(c2), "+f"(c3)
        : "r"(a0), "r"(a1), "r"(a2), "r"(a3), "r"(b0), "r"(b1));
}

__device__ __forceinline__ void ldsm_x4(uint32_t& r0, uint32_t& r1, uint32_t& r2, uint32_t& r3,
                                        uint32_t addr) {
    asm volatile("ldmatrix.sync.aligned.m8n8.x4.shared.b16 {%0,%1,%2,%3}, [%4];"
                 : "=r"(r0), "=r"(r1), "=r"(r2), "=r"(r3) : "r"(addr));
}

// packed fp32 pair FMA (Blackwell sm_100+, PTX 8.6)
__device__ __forceinline__ void fma2(uint64_t& acc, uint64_t a, uint64_t b) {
    asm("fma.rn.f32x2 %0, %1, %2, %0;" : "+l"(acc) : "l"(a), "l"(b));
}
__device__ __forceinline__ float pairsum(uint64_t a) {
    float lo, hi;
    asm("mov.b64 {%0, %1}, %2;" : "=f"(lo), "=f"(hi) : "l"(a));
    return lo + hi;
}

// ---------------- weight transpose -> fp16 ----------------
__global__ void transpose_half_kernel(const float* __restrict__ src, __half* __restrict__ dst,
                                      int R, int Cc) {
    __shared__ float t[32][33];
    const size_t slab = (size_t)R * Cc;
    const float* s = src + (size_t)blockIdx.z * slab;
    __half* d = dst + (size_t)blockIdx.z * slab;
    int c0 = blockIdx.x * 32, r0 = blockIdx.y * 32;
    int x = threadIdx.x, y = threadIdx.y;
#pragma unroll
    for (int i = y; i < 32; i += 8)
        t[i][x] = s[(size_t)(r0 + i) * Cc + c0 + x];
    __syncthreads();
#pragma unroll
    for (int i = y; i < 32; i += 8)
        d[(size_t)(c0 + i) * R + r0 + x] = __float2half(t[x][i]);
}

// ---------------- embedding -> fp16 acts (8 channels/thread, 16B stores) ----------------
__global__ void embed_kernel(const int* __restrict__ x,
                             const unsigned char* __restrict__ m,
                             const float* __restrict__ emb) {
    size_t i8 = (size_t)blockIdx.x * blockDim.x + threadIdx.x;   // over B*T*(C/8)
    size_t bt = i8 >> 6;                 // C/8 = 64 groups per (b,t)
    int c0 = (int)(i8 & 63) * 8;
    int sym = x[bt];
    bool msk = m[bt];
    const float4* er = (const float4*)(emb + (size_t)sym * C_ + c0);
    float4 v0 = er[0], v1 = er[1];
    __half h[8];
    h[0] = __float2half(msk ? 0.f : v0.x); h[1] = __float2half(msk ? 0.f : v0.y);
    h[2] = __float2half(msk ? 0.f : v0.z); h[3] = __float2half(msk ? 0.f : v0.w);
    h[4] = __float2half(msk ? 0.f : v1.x); h[5] = __float2half(msk ? 0.f : v1.y);
    h[6] = __float2half(msk ? 0.f : v1.z); h[7] = __float2half(msk ? 0.f : v1.w);
    *(uint4*)(g_h16 + bt * C_ + c0) = *(const uint4*)h;
}

// ---------------- fp16 mma.sync GEMM / implicit conv (R8 config: 128x128, 4-stage) ----
#define LDKH 40
#define TILEH (128 * LDKH)
#define STAGEH (2 * TILEH)
#define NSTG 4
#define GEMM_SMEM (NSTG * STAGEH * 2)

template <int TAPS>
__global__ __launch_bounds__(256) void mma_gemm_fp16(
    const __half* __restrict__ A,
    const __half* __restrict__ WT, const float* __restrict__ bias, float* __restrict__ Out,
    int Cout,
    const __half* __restrict__ WT2, const float* __restrict__ bias2, float* __restrict__ Out2) {
    extern __shared__ __half shh[];

    if (blockIdx.z) { WT = WT2; bias = bias2; Out = Out2; }

    const int tid = threadIdx.x;
    const int wid = tid >> 5, lane = tid & 31;
    const int r = lane >> 2, cq = lane & 3;
    const int warp_m = wid & 1, warp_n = wid >> 1;
    const int m0 = warp_m * 64, n0 = warp_n * 32;

    const int bb = blockIdx.x >> 3;
    const int t0 = (blockIdx.x & 7) * 128;
    const int co0 = blockIdx.y * 128;
    const int NT = TAPS * 16;
    const int half = (TAPS - 1) / 2;

    float acc[4][4][4];
#pragma unroll
    for (int i = 0; i < 4; i++)
#pragma unroll
        for (int j = 0; j < 4; j++)
#pragma unroll
            for (int k = 0; k < 4; k++) acc[i][j][k] = 0.f;

    const uint32_t shb = smem_u32(shh);

    const uint32_t aOff = (uint32_t)(((m0 + (lane & 15)) * LDKH) * 2 + (lane >> 4) * 16);
    const uint32_t bOff = (uint32_t)(TILEH * 2 +
                         ((n0 + ((lane >> 3) & 1) * 8 + (lane & 7)) * LDKH) * 2 + (lane >> 4) * 16);

    auto load_tile = [&](int tidx, int stage) {
        const uint32_t sbase = shb + stage * (STAGEH * 2);
        const int tap = (TAPS == 1) ? 0 : (tidx >> 4);
        const int kt = (TAPS == 1) ? tidx : (tidx & 15);
        const __half* Ab = A + (size_t)bb * T_ * C_ + kt * 32;
#pragma unroll
        for (int it = 0; it < 2; it++) {
            int chunk = it * 256 + tid;
            int row = chunk >> 2, seg = chunk & 3;
            int t = t0 + row + tap - half;
            int ok = ((unsigned)t < (unsigned)T_) ? 16 : 0;
            int tc = t < 0 ? 0 : (t > T_ - 1 ? T_ - 1 : t);
            cp16(sbase + (row * LDKH + seg * 8) * 2, Ab + (size_t)tc * C_ + seg * 8, ok);
        }
        const __half* Bb = WT + ((size_t)tap * Cout + co0) * C_ + kt * 32;
#pragma unroll
        for (int it = 0; it < 2; it++) {
            int chunk = it * 256 + tid;
            int row = chunk >> 2, seg = chunk & 3;
            cp16(sbase + TILEH * 2 + (row * LDKH + seg * 8) * 2,
                 Bb + (size_t)row * C_ + seg * 8, 16);
        }
    };

    load_tile(0, 0); CP_COMMIT();
    load_tile(1, 1); CP_COMMIT();
    load_tile(2, 2); CP_COMMIT();

    for (int t = 0; t < NT; t++) {
        CP_WAIT2();
        __syncthreads();
        if (t + 3 < NT) load_tile(t + 3, (t + 3) & 3);
        CP_COMMIT();

        const uint32_t stg = shb + (t & 3) * (STAGEH * 2);
#pragma unroll
        for (int ks = 0; ks < 2; ks++) {
            const uint32_t kB = (uint32_t)(ks * 32);
            uint32_t af[4][4], bf[4][2];
#pragma unroll
            for (int i = 0; i < 4; i++)
                ldsm_x4(af[i][0], af[i][1], af[i][2], af[i][3],
                        stg + aOff + (uint32_t)(i * 16 * LDKH * 2) + kB);
#pragma unroll
            for (int jj = 0; jj < 2; jj++)
                ldsm_x4(bf[2 * jj][0], bf[2 * jj + 1][0], bf[2 * jj][1], bf[2 * jj + 1][1],
                        stg + bOff + (uint32_t)(jj * 16 * LDKH * 2) + kB);
#pragma unroll
            for (int i = 0; i < 4; i++)
#pragma unroll
                for (int j = 0; j < 4; j++)
                    mma_f16(acc[i][j][0], acc[i][j][1], acc[i][j][2], acc[i][j][3],
                            af[i][0], af[i][1], af[i][2], af[i][3], bf[j][0], bf[j][1]);
        }
    }

#pragma unroll
    for (int j = 0; j < 4; j++) {
        const int col = co0 + n0 + j * 8 + 2 * cq;
        const float bv0 = bias[col], bv1 = bias[col + 1];
#pragma unroll
        for (int i = 0; i < 4; i++) {
            int row = t0 + m0 + i * 16 + r;
            float2 v0 = make_float2(acc[i][j][0] + bv0, acc[i][j][1] + bv1);
            float2 v1 = make_float2(acc[i][j][2] + bv0, acc[i][j][3] + bv1);
            *(float2*)(Out + ((size_t)bb * T_ + row) * Cout + col) = v0;
            *(float2*)(Out + ((size_t)bb * T_ + row + 8) * Cout + col) = v1;
        }
    }
}

// ---------------- LayerNorm over time + leaky relu + mask (4 channels/thread) ---------
__global__ void ln_lrelu_kernel(const float* __restrict__ h, __half* __restrict__ o16,
                                const float* __restrict__ scale,
                                const float* __restrict__ bias,
                                const unsigned char* __restrict__ m) {
    const int b = blockIdx.x;
    const int c = threadIdx.x * 4;            // 128 threads x 4 = 512 channels
    const float4* hb = (const float4*)(h + (size_t)b * T_ * C_ + c);
    __half* ob = o16 + (size_t)b * T_ * C_ + c;
    float4 s = make_float4(0.f, 0.f, 0.f, 0.f);
    float4 s2 = make_float4(0.f, 0.f, 0.f, 0.f);
#pragma unroll 4
    for (int t = 0; t < T_; t++) {
        float4 v = hb[(size_t)t * (C_ / 4)];
        s.x += v.x; s.y += v.y; s.z += v.z; s.w += v.w;
        s2.x += v.x * v.x; s2.y += v.y * v.y; s2.z += v.z * v.z; s2.w += v.w * v.w;
    }
    const float inv = 1.f / T_;
    float4 mu = make_float4(s.x * inv, s.y * inv, s.z * inv, s.w * inv);
    float4 rs;
    rs.x = rsqrtf(s2.x * inv - mu.x * mu.x + 1e-5f);
    rs.y = rsqrtf(s2.y * inv - mu.y * mu.y + 1e-5f);
    rs.z = rsqrtf(s2.z * inv - mu.z * mu.z + 1e-5f);
    rs.w = rsqrtf(s2.w * inv - mu.w * mu.w + 1e-5f);
    const unsigned char* mb = m + (size_t)b * T_;
#pragma unroll 2
    for (int t = 0; t < T_; t++) {
        float4 v = hb[(size_t)t * (C_ / 4)];
        const float sc = scale[t], bi = bias[t];
        float o[4];
        o[0] = (v.x - mu.x) * rs.x * sc + bi;
        o[1] = (v.y - mu.y) * rs.y * sc + bi;
        o[2] = (v.z - mu.z) * rs.z * sc + bi;
        o[3] = (v.w - mu.w) * rs.w * sc + bi;
        const bool msk = mb[t];
        __half hh[4];
#pragma unroll
        for (int k = 0; k < 4; k++) {
            float vv = (o[k] > 0.f) ? o[k] : 0.2f * o[k];
            hh[k] = __float2half(msk ? 0.f : vv);
        }
        *(uint2*)(ob + (size_t)t * C_) = *(const uint2*)hh;
    }
}

// ---------------- flag reset (graph-replay safe) ----------------
__global__ void reset_flags_kernel() {
    if (threadIdx.x < 128) g_flags[threadIdx.x] = 0;
}

// ---------------- bidirectional LSTM recurrence (R7 champion, verbatim) --------------
__global__ __launch_bounds__(512) void lstm_kernel(const float* __restrict__ wh_fw,
                                                   const float* __restrict__ wh_bw) {
    __shared__ float hps[1024];          // [4 batch][256]
    __shared__ float part[4 * 4 * 128];  // [kq][bl][g]
    __shared__ float cbuf[128];          // [bi][u]

    const int tid = threadIdx.x;
    const int dir = blockIdx.x >> 6;
    const int bg = (blockIdx.x >> 3) & 7;
    const int hg = blockIdx.x & 7;
    const int u0 = hg * 32;
    const int b0 = bg * 4;

    const int g = tid & 127;
    const int kq = tid >> 7;
    const int q = g >> 5;
    const int j = g & 31;
    const int col = q * 256 + u0 + j;

    const float* wh = dir ? wh_bw : wh_fw;
    uint64_t wreg[32];
#pragma unroll
    for (int k2 = 0; k2 < 32; k2++) {
        float w0 = wh[(size_t)(kq * 64 + 2 * k2) * 1024 + col];
        float w1 = wh[(size_t)(kq * 64 + 2 * k2 + 1) * 1024 + col];
        asm("mov.b64 %0, {%1, %2};" : "=l"(wreg[k2]) : "f"(w0), "f"(w1));
    }

    for (int i = tid; i < 1024; i += 512) hps[i] = 0.f;
    if (tid < 128) cbuf[tid] = 0.f;
    __syncthreads();

    const int u = tid & 31;
    const int bi = (tid >> 5) & 3;

    const float* xgd = g_xg + (size_t)dir * B_ * T_ * 1024;
    float* hsd = g_hs + (size_t)dir * T_ * B_ * H_;
    volatile unsigned int* flg = (volatile unsigned int*)(g_flags + dir * 64 + bg * 8);

    for (int s = 0; s < T_; s++) {
        const int t = dir ? (T_ - 1 - s) : s;
        float xv = xgd[((size_t)(b0 + kq) * T_ + t) * 1024 + col];

        if (s > 0) {
            if (tid < 8) {
                while (flg[tid] < (unsigned)s) { }
            }
            __syncthreads();
            const int tprev = dir ? (t + 1) : (t - 1);
            const float2* src = (const float2*)(hsd + ((size_t)tprev * B_ + b0) * H_);
            ((float2*)hps)[tid] = __ldcg(src + tid);
        }
        __syncthreads();

        const float* hq = hps + kq * 64;
        uint64_t a0 = 0, a1 = 0, a2 = 0, a3 = 0;
#pragma unroll
        for (int k2 = 0; k2 < 64; k2 += 4) {
            union U { float4 f; uint64_t u[2]; };
            U ha, hb, hc, hd;
            ha.f = *(const float4*)(hq + k2);
            hb.f = *(const float4*)(hq + 256 + k2);
            hc.f = *(const float4*)(hq + 512 + k2);
            hd.f = *(const float4*)(hq + 768 + k2);
            uint64_t w0 = wreg[k2 >> 1], w1 = wreg[(k2 >> 1) + 1];
            fma2(a0, w0, ha.u[0]); fma2(a0, w1, ha.u[1]);
            fma2(a1, w0, hb.u[0]); fma2(a1, w1, hb.u[1]);
            fma2(a2, w0, hc.u[0]); fma2(a2, w1, hc.u[1]);
            fma2(a3, w0, hd.u[0]); fma2(a3, w1, hd.u[1]);
        }
        part[(kq * 4 + 0) * 128 + g] = pairsum(a0) + ((kq == 0) ? xv : 0.f);
        part[(kq * 4 + 1) * 128 + g] = pairsum(a1) + ((kq == 1) ? xv : 0.f);
        part[(kq * 4 + 2) * 128 + g] = pairsum(a2) + ((kq == 2) ? xv : 0.f);
        part[(kq * 4 + 3) * 128 + g] = pairsum(a3) + ((kq == 3) ? xv : 0.f);
        __syncthreads();

        if (tid < 128) {
            float gate[4];
#pragma unroll
            for (int qq = 0; qq < 4; qq++) {
                float sum = part[(0 * 4 + bi) * 128 + qq * 32 + u]
                          + part[(1 * 4 + bi) * 128 + qq * 32 + u]
                          + part[(2 * 4 + bi) * 128 + qq * 32 + u]
                          + part[(3 * 4 + bi) * 128 + qq * 32 + u];
                gate[qq] = (qq == 2) ? tanhf(sum) : (1.f / (1.f + expf(-sum)));
            }
            float cc = gate[1] * cbuf[tid] + gate[0] * gate[2];
            cbuf[tid] = cc;
            float hn = gate[3] * tanhf(cc);
            hsd[((size_t)t * B_ + b0 + bi) * H_ + u0 + u] = hn;
            __threadfence();
        }
        __syncthreads();
        if (tid == 0) flg[hg] = (unsigned)(s + 1);
    }
}

// ---------------- output transpose [2][T][B][H] -> [B, 2H, T] ----------------
__global__ void out_kernel(float* __restrict__ out, const unsigned char* __restrict__ m) {
    const int dir = blockIdx.y >> 3;
    const int h0 = (blockIdx.y & 7) * 32;
    const int t0 = blockIdx.x * 32;
    const int b = blockIdx.z;
    __shared__ float tile[32][33];
    const float* hsd = g_hs + (size_t)dir * T_ * B_ * H_;
    const int tx = threadIdx.x, ty = threadIdx.y;
#pragma unroll
    for (int r = 0; r < 32; r += 8) {
        int t = t0 + ty + r;
        tile[ty + r][tx] = hsd[((size_t)t * B_ + b) * H_ + h0 + tx];
    }
    __syncthreads();
#pragma unroll
    for (int r = 0; r < 32; r += 8) {
        int hh = ty + r;
        int c = dir * H_ + h0 + hh;
        int t = t0 + tx;
        float v = tile[tx][hh];
        if (m[(size_t)b * T_ + t]) v = 0.f;
        out[((size_t)b * C_ + c) * T_ + t] = v;
    }
}

// ---------------- launch ----------------
extern "C" void kernel_launch(void* const* d_in, const int* in_sizes, int n_in,
                              void* d_out, int out_size) {
    const int* x = (const int*)d_in[0];
    const unsigned char* m = (const unsigned char*)d_in[2];
    const float* emb = (const float*)d_in[3];
    const float* conv_w = (const float*)d_in[4];
    const float* conv_b = (const float*)d_in[5];
    const float* ln_scale = (const float*)d_in[6];
    const float* ln_bias = (const float*)d_in[7];
    const float* wx_fw = (const float*)d_in[8];
    const float* wh_fw = (const float*)d_in[9];
    const float* b_fw = (const float*)d_in[10];
    const float* wx_bw = (const float*)d_in[11];
    const float* wh_bw = (const float*)d_in[12];
    const float* b_bw = (const float*)d_in[13];
    float* out = (float*)d_out;

    float *bufA, *xg;
    __half *h16, *wT16, *wxT16;
    cudaGetSymbolAddress((void**)&bufA, g_bufA);
    cudaGetSymbolAddress((void**)&xg, g_xg);
    cudaGetSymbolAddress((void**)&h16, g_h16);
    cudaGetSymbolAddress((void**)&wT16, g_wT16);
    cudaGetSymbolAddress((void**)&wxT16, g_wxT16);

    cudaFuncSetAttribute(mma_gemm_fp16<5>, cudaFuncAttributeMaxDynamicSharedMemorySize, GEMM_SMEM);
    cudaFuncSetAttribute(mma_gemm_fp16<1>, cudaFuncAttributeMaxDynamicSharedMemorySize, GEMM_SMEM);

    // launch order keeps the first conv GEMM at the ncu capture slot (my 4th launch)
    embed_kernel<<<(int)(((size_t)B_ * T_ * C_) / 8 / 256), 256>>>(x, m, emb);
    transpose_half_kernel<<<dim3(16, 16, 15), dim3(32, 8)>>>(conv_w, wT16, 512, 512);
    transpose_half_kernel<<<dim3(32, 16, 1), dim3(32, 8)>>>(wx_fw, wxT16, 512, 1024);

    for (int d = 0; d < 3; d++) {
        mma_gemm_fp16<5><<<dim3(B_ * 8, 4, 1), 256, GEMM_SMEM>>>(
            h16, wT16 + (size_t)d * 5 * 512 * 512, conv_b + (size_t)d * 512, bufA, 512,
            wT16, conv_b, bufA);
        ln_lrelu_kernel<<<B_, 128>>>(bufA, h16, ln_scale + (size_t)d * T_,
                                     ln_bias + (size_t)d * T_, m);
    }

    transpose_half_kernel<<<dim3(32, 16, 1), dim3(32, 8)>>>(wx_bw, wxT16 + (size_t)1024 * 512, 512, 1024);

    mma_gemm_fp16<1><<<dim3(B_ * 8, 8, 2), 256, GEMM_SMEM>>>(
        h16, wxT16, b_fw, xg, 1024,
        wxT16 + (size_t)1024 * 512, b_bw, xg + (size_t)B_ * T_ * 1024);

    // recurrence (regs-W, f32x2, R7 L2 flag exchange)
    reset_flags_kernel<<<1, 128>>>();
    lstm_kernel<<<128, 512>>>(wh_fw, wh_bw);

    out_kernel<<<dim3(T_ / 32, 16, B_), dim3(32, 8)>>>(out, m);
}

// round 16
// speedup vs baseline: 1.3383x; 1.2428x over previous
#include <cuda_runtime.h>
#include <cuda_fp16.h>
#include <math.h>
#include <stdint.h>

#define B_ 32
#define T_ 1024
#define C_ 512
#define H_ 256

// ---------------- static device scratch ----------------
__device__ float g_bufA[(size_t)B_ * T_ * C_];                 // fp32 conv output
__device__ __half g_h16[(size_t)B_ * T_ * C_];                 // fp16 GEMM input acts
__device__ float g_xg[(size_t)2 * B_ * T_ * 4 * H_];
__device__ float g_hs[(size_t)2 * T_ * B_ * H_];
__device__ __half g_wT16[(size_t)3 * 5 * 512 * 512];           // conv W [d][tap][co][ci] fp16
__device__ __half g_wxT16[(size_t)2 * 1024 * 512];             // wx [dir][gatecol][ci] fp16
__device__ unsigned int g_flags[128];

// ---------------- helpers ----------------
__device__ __forceinline__ uint32_t smem_u32(const void* p) {
    uint32_t a;
    asm("{ .reg .u64 t; cvta.to.shared.u64 t, %1; cvt.u32.u64 %0, t; }" : "=r"(a) : "l"(p));
    return a;
}
__device__ __forceinline__ void cp16(uint32_t dst, const void* src, int srcsz) {
    asm volatile("cp.async.cg.shared.global [%0], [%1], 16, %2;"
                 :: "r"(dst), "l"(src), "r"(srcsz));
}
#define CP_COMMIT() asm volatile("cp.async.commit_group;")
#define CP_WAIT2()  asm volatile("cp.async.wait_group 2;")

__device__ __forceinline__ void mma_f16(float& c0, float& c1, float& c2, float& c3,
                                        uint32_t a0, uint32_t a1, uint32_t a2, uint32_t a3,
                                        uint32_t b0, uint32_t b1) {
    asm volatile(
        "mma.sync.aligned.m16n8k16.row.col.f32.f16.f16.f32 "
        "{%0,%1,%2,%3}, {%4,%5,%6,%7}, {%8,%9}, {%0,%1,%2,%3};"
        : "+f"(c0), "+f"(c1), "+f"(c2), "+f"(c3)
        : "r"(a0), "r"(a1), "r"(a2), "r"(a3), "r"(b0), "r"(b1));
}

__device__ __forceinline__ void ldsm_x4(uint32_t& r0, uint32_t& r1, uint32_t& r2, uint32_t& r3,
                                        uint32_t addr) {
    asm volatile("ldmatrix.sync.aligned.m8n8.x4.shared.b16 {%0,%1,%2,%3}, [%4];"
                 : "=r"(r0), "=r"(r1), "=r"(r2), "=r"(r3) : "r"(addr));
}

// packed fp32 pair FMA (Blackwell sm_100+, PTX 8.6)
__device__ __forceinline__ void fma2(uint64_t& acc, uint64_t a, uint64_t b) {
    asm("fma.rn.f32x2 %0, %1, %2, %0;" : "+l"(acc) : "l"(a), "l"(b));
}
__device__ __forceinline__ float pairsum(uint64_t a) {
    float lo, hi;
    asm("mov.b64 {%0, %1}, %2;" : "=f"(lo), "=f"(hi) : "l"(a));
    return lo + hi;
}

// fast activations via MUFU (error ~1e-6, negligible vs 7e-4 budget)
__device__ __forceinline__ float fast_sigmoid(float x) {
    return __fdividef(1.f, 1.f + __expf(-x));
}
__device__ __forceinline__ float fast_tanh(float x) {
    return __fdividef(2.f, 1.f + __expf(-2.f * x)) - 1.f;
}

// ---------------- weight transpose -> fp16 ----------------
__global__ void transpose_half_kernel(const float* __restrict__ src, __half* __restrict__ dst,
                                      int R, int Cc) {
    __shared__ float t[32][33];
    const size_t slab = (size_t)R * Cc;
    const float* s = src + (size_t)blockIdx.z * slab;
    __half* d = dst + (size_t)blockIdx.z * slab;
    int c0 = blockIdx.x * 32, r0 = blockIdx.y * 32;
    int x = threadIdx.x, y = threadIdx.y;
#pragma unroll
    for (int i = y; i < 32; i += 8)
        t[i][x] = s[(size_t)(r0 + i) * Cc + c0 + x];
    __syncthreads();
#pragma unroll
    for (int i = y; i < 32; i += 8)
        d[(size_t)(c0 + i) * R + r0 + x] = __float2half(t[x][i]);
}

// ---------------- embedding -> fp16 acts (8 channels/thread, 16B stores) ----------------
__global__ void embed_kernel(const int* __restrict__ x,
                             const unsigned char* __restrict__ m,
                             const float* __restrict__ emb) {
    size_t i8 = (size_t)blockIdx.x * blockDim.x + threadIdx.x;   // over B*T*(C/8)
    size_t bt = i8 >> 6;
    int c0 = (int)(i8 & 63) * 8;
    int sym = x[bt];
    bool msk = m[bt];
    const float4* er = (const float4*)(emb + (size_t)sym * C_ + c0);
    float4 v0 = er[0], v1 = er[1];
    __half h[8];
    h[0] = __float2half(msk ? 0.f : v0.x); h[1] = __float2half(msk ? 0.f : v0.y);
    h[2] = __float2half(msk ? 0.f : v0.z); h[3] = __float2half(msk ? 0.f : v0.w);
    h[4] = __float2half(msk ? 0.f : v1.x); h[5] = __float2half(msk ? 0.f : v1.y);
    h[6] = __float2half(msk ? 0.f : v1.z); h[7] = __float2half(msk ? 0.f : v1.w);
    *(uint4*)(g_h16 + bt * C_ + c0) = *(const uint4*)h;
}

// ---------------- fp16 mma.sync GEMM / implicit conv (R8-frozen: 128x128, 4-stage) ----
#define LDKH 40
#define TILEH (128 * LDKH)
#define STAGEH (2 * TILEH)
#define NSTG 4
#define GEMM_SMEM (NSTG * STAGEH * 2)

template <int TAPS>
__global__ __launch_bounds__(256) void mma_gemm_fp16(
    const __half* __restrict__ A,
    const __half* __restrict__ WT, const float* __restrict__ bias, float* __restrict__ Out,
    int Cout,
    const __half* __restrict__ WT2, const float* __restrict__ bias2, float* __restrict__ Out2) {
    extern __shared__ __half shh[];

    if (blockIdx.z) { WT = WT2; bias = bias2; Out = Out2; }

    const int tid = threadIdx.x;
    const int wid = tid >> 5, lane = tid & 31;
    const int r = lane >> 2, cq = lane & 3;
    const int warp_m = wid & 1, warp_n = wid >> 1;
    const int m0 = warp_m * 64, n0 = warp_n * 32;

    const int bb = blockIdx.x >> 3;
    const int t0 = (blockIdx.x & 7) * 128;
    const int co0 = blockIdx.y * 128;
    const int NT = TAPS * 16;
    const int half = (TAPS - 1) / 2;

    float acc[4][4][4];
#pragma unroll
    for (int i = 0; i < 4; i++)
#pragma unroll
        for (int j = 0; j < 4; j++)
#pragma unroll
            for (int k = 0; k < 4; k++) acc[i][j][k] = 0.f;

    const uint32_t shb = smem_u32(shh);

    const uint32_t aOff = (uint32_t)(((m0 + (lane & 15)) * LDKH) * 2 + (lane >> 4) * 16);
    const uint32_t bOff = (uint32_t)(TILEH * 2 +
                         ((n0 + ((lane >> 3) & 1) * 8 + (lane & 7)) * LDKH) * 2 + (lane >> 4) * 16);

    auto load_tile = [&](int tidx, int stage) {
        const uint32_t sbase = shb + stage * (STAGEH * 2);
        const int tap = (TAPS == 1) ? 0 : (tidx >> 4);
        const int kt = (TAPS == 1) ? tidx : (tidx & 15);
        const __half* Ab = A + (size_t)bb * T_ * C_ + kt * 32;
#pragma unroll
        for (int it = 0; it < 2; it++) {
            int chunk = it * 256 + tid;
            int row = chunk >> 2, seg = chunk & 3;
            int t = t0 + row + tap - half;
            int ok = ((unsigned)t < (unsigned)T_) ? 16 : 0;
            int tc = t < 0 ? 0 : (t > T_ - 1 ? T_ - 1 : t);
            cp16(sbase + (row * LDKH + seg * 8) * 2, Ab + (size_t)tc * C_ + seg * 8, ok);
        }
        const __half* Bb = WT + ((size_t)tap * Cout + co0) * C_ + kt * 32;
#pragma unroll
        for (int it = 0; it < 2; it++) {
            int chunk = it * 256 + tid;
            int row = chunk >> 2, seg = chunk & 3;
            cp16(sbase + TILEH * 2 + (row * LDKH + seg * 8) * 2,
                 Bb + (size_t)row * C_ + seg * 8, 16);
        }
    };

    load_tile(0, 0); CP_COMMIT();
    load_tile(1, 1); CP_COMMIT();
    load_tile(2, 2); CP_COMMIT();

    for (int t = 0; t < NT; t++) {
        CP_WAIT2();
        __syncthreads();
        if (t + 3 < NT) load_tile(t + 3, (t + 3) & 3);
        CP_COMMIT();

        const uint32_t stg = shb + (t & 3) * (STAGEH * 2);
#pragma unroll
        for (int ks = 0; ks < 2; ks++) {
            const uint32_t kB = (uint32_t)(ks * 32);
            uint32_t af[4][4], bf[4][2];
#pragma unroll
            for (int i = 0; i < 4; i++)
                ldsm_x4(af[i][0], af[i][1], af[i][2], af[i][3],
                        stg + aOff + (uint32_t)(i * 16 * LDKH * 2) + kB);
#pragma unroll
            for (int jj = 0; jj < 2; jj++)
                ldsm_x4(bf[2 * jj][0], bf[2 * jj + 1][0], bf[2 * jj][1], bf[2 * jj + 1][1],
                        stg + bOff + (uint32_t)(jj * 16 * LDKH * 2) + kB);
#pragma unroll
            for (int i = 0; i < 4; i++)
#pragma unroll
                for (int j = 0; j < 4; j++)
                    mma_f16(acc[i][j][0], acc[i][j][1], acc[i][j][2], acc[i][j][3],
                            af[i][0], af[i][1], af[i][2], af[i][3], bf[j][0], bf[j][1]);
        }
    }

#pragma unroll
    for (int j = 0; j < 4; j++) {
        const int col = co0 + n0 + j * 8 + 2 * cq;
        const float bv0 = bias[col], bv1 = bias[col + 1];
#pragma unroll
        for (int i = 0; i < 4; i++) {
            int row = t0 + m0 + i * 16 + r;
            float2 v0 = make_float2(acc[i][j][0] + bv0, acc[i][j][1] + bv1);
            float2 v1 = make_float2(acc[i][j][2] + bv0, acc[i][j][3] + bv1);
            *(float2*)(Out + ((size_t)bb * T_ + row) * Cout + col) = v0;
            *(float2*)(Out + ((size_t)bb * T_ + row + 8) * Cout + col) = v1;
        }
    }
}

// ---------------- LayerNorm over time + leaky relu + mask (R7-exact form) -------------
__global__ void ln_lrelu_kernel(const float* __restrict__ h, __half* __restrict__ o16,
                                const float* __restrict__ scale,
                                const float* __restrict__ bias,
                                const unsigned char* __restrict__ m) {
    const int b = blockIdx.x;
    const int c = blockIdx.y * 128 + threadIdx.x;
    const float* hb = h + (size_t)b * T_ * C_ + c;
    __half* ob = o16 + (size_t)b * T_ * C_ + c;
    float s = 0.f, s2 = 0.f;
#pragma unroll 8
    for (int t = 0; t < T_; t++) {
        float v = hb[(size_t)t * C_];
        s += v; s2 += v * v;
    }
    const float mu = s * (1.f / T_);
    const float var = s2 * (1.f / T_) - mu * mu;
    const float rs = rsqrtf(var + 1e-5f);
    const unsigned char* mb = m + (size_t)b * T_;
#pragma unroll 4
    for (int t = 0; t < T_; t++) {
        float v = hb[(size_t)t * C_];
        v = (v - mu) * rs * scale[t] + bias[t];
        v = (v > 0.f) ? v : 0.2f * v;
        if (mb[t]) v = 0.f;
        ob[(size_t)t * C_] = __float2half(v);
    }
}

// ---------------- flag reset (graph-replay safe) ----------------
__global__ void reset_flags_kernel() {
    if (threadIdx.x < 128) g_flags[threadIdx.x] = 0;
}

// ---------------- bidirectional LSTM recurrence (R7 champion + fast activations) -----
__global__ __launch_bounds__(512) void lstm_kernel(const float* __restrict__ wh_fw,
                                                   const float* __restrict__ wh_bw) {
    __shared__ float hps[1024];          // [4 batch][256]
    __shared__ float part[4 * 4 * 128];  // [kq][bl][g]
    __shared__ float cbuf[128];          // [bi][u]

    const int tid = threadIdx.x;
    const int dir = blockIdx.x >> 6;
    const int bg = (blockIdx.x >> 3) & 7;
    const int hg = blockIdx.x & 7;
    const int u0 = hg * 32;
    const int b0 = bg * 4;

    const int g = tid & 127;
    const int kq = tid >> 7;
    const int q = g >> 5;
    const int j = g & 31;
    const int col = q * 256 + u0 + j;

    const float* wh = dir ? wh_bw : wh_fw;
    uint64_t wreg[32];
#pragma unroll
    for (int k2 = 0; k2 < 32; k2++) {
        float w0 = wh[(size_t)(kq * 64 + 2 * k2) * 1024 + col];
        float w1 = wh[(size_t)(kq * 64 + 2 * k2 + 1) * 1024 + col];
        asm("mov.b64 %0, {%1, %2};" : "=l"(wreg[k2]) : "f"(w0), "f"(w1));
    }

    for (int i = tid; i < 1024; i += 512) hps[i] = 0.f;
    if (tid < 128) cbuf[tid] = 0.f;
    __syncthreads();

    const int u = tid & 31;
    const int bi = (tid >> 5) & 3;

    const float* xgd = g_xg + (size_t)dir * B_ * T_ * 1024;
    float* hsd = g_hs + (size_t)dir * T_ * B_ * H_;
    volatile unsigned int* flg = (volatile unsigned int*)(g_flags + dir * 64 + bg * 8);

    for (int s = 0; s < T_; s++) {
        const int t = dir ? (T_ - 1 - s) : s;
        float xv = xgd[((size_t)(b0 + kq) * T_ + t) * 1024 + col];

        if (s > 0) {
            if (tid < 8) {
                while (flg[tid] < (unsigned)s) { }
            }
            __syncthreads();
            const int tprev = dir ? (t + 1) : (t - 1);
            const float2* src = (const float2*)(hsd + ((size_t)tprev * B_ + b0) * H_);
            ((float2*)hps)[tid] = __ldcg(src + tid);
        }
        __syncthreads();

        const float* hq = hps + kq * 64;
        uint64_t a0 = 0, a1 = 0, a2 = 0, a3 = 0;
#pragma unroll
        for (int k2 = 0; k2 < 64; k2 += 4) {
            union U { float4 f; uint64_t u[2]; };
            U ha, hb, hc, hd;
            ha.f = *(const float4*)(hq + k2);
            hb.f = *(const float4*)(hq + 256 + k2);
            hc.f = *(const float4*)(hq + 512 + k2);
            hd.f = *(const float4*)(hq + 768 + k2);
            uint64_t w0 = wreg[k2 >> 1], w1 = wreg[(k2 >> 1) + 1];
            fma2(a0, w0, ha.u[0]); fma2(a0, w1, ha.u[1]);
            fma2(a1, w0, hb.u[0]); fma2(a1, w1, hb.u[1]);
            fma2(a2, w0, hc.u[0]); fma2(a2, w1, hc.u[1]);
            fma2(a3, w0, hd.u[0]); fma2(a3, w1, hd.u[1]);
        }
        part[(kq * 4 + 0) * 128 + g] = pairsum(a0) + ((kq == 0) ? xv : 0.f);
        part[(kq * 4 + 1) * 128 + g] = pairsum(a1) + ((kq == 1) ? xv : 0.f);
        part[(kq * 4 + 2) * 128 + g] = pairsum(a2) + ((kq == 2) ? xv : 0.f);
        part[(kq * 4 + 3) * 128 + g] = pairsum(a3) + ((kq == 3) ? xv : 0.f);
        __syncthreads();

        if (tid < 128) {
            float gate[4];
#pragma unroll
            for (int qq = 0; qq < 4; qq++) {
                float sum = part[(0 * 4 + bi) * 128 + qq * 32 + u]
                          + part[(1 * 4 + bi) * 128 + qq * 32 + u]
                          + part[(2 * 4 + bi) * 128 + qq * 32 + u]
                          + part[(3 * 4 + bi) * 128 + qq * 32 + u];
                gate[qq] = (qq == 2) ? fast_tanh(sum) : fast_sigmoid(sum);
            }
            float cc = gate[1] * cbuf[tid] + gate[0] * gate[2];
            cbuf[tid] = cc;
            float hn = gate[3] * fast_tanh(cc);
            hsd[((size_t)t * B_ + b0 + bi) * H_ + u0 + u] = hn;
            __threadfence();
        }
        __syncthreads();
        if (tid == 0) flg[hg] = (unsigned)(s + 1);
    }
}

// ---------------- output transpose [2][T][B][H] -> [B, 2H, T] ----------------
__global__ void out_kernel(float* __restrict__ out, const unsigned char* __restrict__ m) {
    const int dir = blockIdx.y >> 3;
    const int h0 = (blockIdx.y & 7) * 32;
    const int t0 = blockIdx.x * 32;
    const int b = blockIdx.z;
    __shared__ float tile[32][33];
    const float* hsd = g_hs + (size_t)dir * T_ * B_ * H_;
    const int tx = threadIdx.x, ty = threadIdx.y;
#pragma unroll
    for (int r = 0; r < 32; r += 8) {
        int t = t0 + ty + r;
        tile[ty + r][tx] = hsd[((size_t)t * B_ + b) * H_ + h0 + tx];
    }
    __syncthreads();
#pragma unroll
    for (int r = 0; r < 32; r += 8) {
        int hh = ty + r;
        int c = dir * H_ + h0 + hh;
        int t = t0 + tx;
        float v = tile[tx][hh];
        if (m[(size_t)b * T_ + t]) v = 0.f;
        out[((size_t)b * C_ + c) * T_ + t] = v;
    }
}

// ---------------- launch ----------------
extern "C" void kernel_launch(void* const* d_in, const int* in_sizes, int n_in,
                              void* d_out, int out_size) {
    const int* x = (const int*)d_in[0];
    const unsigned char* m = (const unsigned char*)d_in[2];
    const float* emb = (const float*)d_in[3];
    const float* conv_w = (const float*)d_in[4];
    const float* conv_b = (const float*)d_in[5];
    const float* ln_scale = (const float*)d_in[6];
    const float* ln_bias = (const float*)d_in[7];
    const float* wx_fw = (const float*)d_in[8];
    const float* wh_fw = (const float*)d_in[9];
    const float* b_fw = (const float*)d_in[10];
    const float* wx_bw = (const float*)d_in[11];
    const float* wh_bw = (const float*)d_in[12];
    const float* b_bw = (const float*)d_in[13];
    float* out = (float*)d_out;

    float *bufA, *xg;
    __half *h16, *wT16, *wxT16;
    cudaGetSymbolAddress((void**)&bufA, g_bufA);
    cudaGetSymbolAddress((void**)&xg, g_xg);
    cudaGetSymbolAddress((void**)&h16, g_h16);
    cudaGetSymbolAddress((void**)&wT16, g_wT16);
    cudaGetSymbolAddress((void**)&wxT16, g_wxT16);

    cudaFuncSetAttribute(mma_gemm_fp16<5>, cudaFuncAttributeMaxDynamicSharedMemorySize, GEMM_SMEM);
    cudaFuncSetAttribute(mma_gemm_fp16<1>, cudaFuncAttributeMaxDynamicSharedMemorySize, GEMM_SMEM);

    // launch order keeps the first conv GEMM at the ncu capture slot (my 4th launch)
    reset_flags_kernel<<<1, 128>>>();
    embed_kernel<<<(int)(((size_t)B_ * T_ * C_) / 8 / 256), 256>>>(x, m, emb);
    transpose_half_kernel<<<dim3(16, 16, 15), dim3(32, 8)>>>(conv_w, wT16, 512, 512);

    for (int d = 0; d < 3; d++) {
        mma_gemm_fp16<5><<<dim3(B_ * 8, 4, 1), 256, GEMM_SMEM>>>(
            h16, wT16 + (size_t)d * 5 * 512 * 512, conv_b + (size_t)d * 512, bufA, 512,
            wT16, conv_b, bufA);
        ln_lrelu_kernel<<<dim3(B_, 4), 128>>>(bufA, h16, ln_scale + (size_t)d * T_,
                                              ln_bias + (size_t)d * T_, m);
    }

    transpose_half_kernel<<<dim3(32, 16, 1), dim3(32, 8)>>>(wx_fw, wxT16, 512, 1024);
    transpose_half_kernel<<<dim3(32, 16, 1), dim3(32, 8)>>>(wx_bw, wxT16 + (size_t)1024 * 512, 512, 1024);

    mma_gemm_fp16<1><<<dim3(B_ * 8, 8, 2), 256, GEMM_SMEM>>>(
        h16, wxT16, b_fw, xg, 1024,
        wxT16 + (size_t)1024 * 512, b_bw, xg + (size_t)B_ * T_ * 1024);

    // recurrence (R7 exchange, fast activations)
    lstm_kernel<<<128, 512>>>(wh_fw, wh_bw);

    out_kernel<<<dim3(T_ / 32, 16, B_), dim3(32, 8)>>>(out, m);
}